// round 2
// baseline (speedup 1.0000x reference)
#include <cuda_runtime.h>
#include <math.h>
#include <float.h>

#define NN 100000
#define NE 800000
#define NG 64

// ---------------- scratch pool (device globals; resolved device-side) ----------------
// B0..B5: node-feature buffers with lifetime reuse. Total ~490 MB.
__device__ float g_B0[NN * 192];   // x1_res (live whole encoder)
__device__ float g_B1[NN * 192];   // agg (reused for every scatter)
__device__ float g_B2[NN * 256];   // h -> c -> tmp -> t
__device__ float g_B3[NN * 192];   // hw -> gate -> t2
__device__ float g_B4[NN * 192];   // h2 -> z
__device__ float g_B5[NN * 192];   // c2 -> z1_res
__device__ float g_deg [NN];
__device__ float g_dinv[NN];
__device__ float g_small[4 * NG * 192];  // zg | gmax | esum | zgw

#define SEL_ZG   16
#define SEL_GMAX 17
#define SEL_ESUM 18
#define SEL_ZGW  19

__device__ __forceinline__ float* scratch(int id) {
    switch (id) {
        case 0:  return g_B0;
        case 1:  return g_B1;
        case 2:  return g_B2;
        case 3:  return g_B3;
        case 4:  return g_B4;
        case 5:  return g_B5;
        case SEL_ZG:   return g_small;
        case SEL_GMAX: return g_small + NG * 192;
        case SEL_ESUM: return g_small + 2 * NG * 192;
        case SEL_ZGW:  return g_small + 3 * NG * 192;
        default: return nullptr;
    }
}

// ---------------- small utility kernels ----------------
__global__ void fill_kernel(int sel, float v, int n4) {
    int i = blockIdx.x * blockDim.x + threadIdx.x;
    if (i < n4) ((float4*)scratch(sel))[i] = make_float4(v, v, v, v);
}

__global__ void deg_zero_kernel() {
    int i = blockIdx.x * blockDim.x + threadIdx.x;
    if (i < NN) g_deg[i] = 0.f;
}

__global__ void deg_kernel(const int* __restrict__ dst) {
    int e = blockIdx.x * blockDim.x + threadIdx.x;
    if (e < NE) atomicAdd(&g_deg[dst[e]], 1.0f);
}

__global__ void dinv_kernel() {
    int i = blockIdx.x * blockDim.x + threadIdx.x;
    if (i < NN) g_dinv[i] = rsqrtf(g_deg[i] + 1.0f);
}

// o = a + b + c (elementwise), all scratch sels; o may alias a
__global__ void add3_kernel(int aSel, int bSel, int cSel, int oSel, int n) {
    int i = blockIdx.x * blockDim.x + threadIdx.x;
    if (i < n) {
        const float* a = scratch(aSel);
        const float* b = scratch(bSel);
        const float* c = scratch(cSel);
        scratch(oSel)[i] = a[i] + b[i] + c[i];
    }
}

// ---------------- SGEMM: C = act(A @ B + bias) (+res) ----------------
// BM=BN=64, BK=16, 256 threads, 4x4 micro-tile. K % 16 == 0, N % 64 == 0.
__global__ __launch_bounds__(256)
void sgemm_kernel(int M, int N, int K,
                  const float* __restrict__ Aext, int Asel,
                  const float* __restrict__ B,
                  const float* __restrict__ bias,
                  int resSel,
                  float* __restrict__ Cext, int Csel,
                  int relu) {
    const int BM = 64, BN = 64, BK = 16;
    __shared__ float As[BK][BM];
    __shared__ float Bs[BK][BN];

    const float* A = Aext ? Aext : scratch(Asel);
    float* C = Cext ? Cext : scratch(Csel);
    const float* res = (resSel >= 0) ? scratch(resSel) : nullptr;

    int tid = threadIdx.x;
    int bm0 = blockIdx.y * BM;
    int bn0 = blockIdx.x * BN;
    int tx = tid & 15;
    int ty = tid >> 4;

    int aRow  = tid >> 2;
    int aCol4 = (tid & 3) << 2;
    int bRow  = tid >> 4;
    int bCol4 = (tid & 15) << 2;

    float acc[4][4];
#pragma unroll
    for (int i = 0; i < 4; i++)
#pragma unroll
        for (int j = 0; j < 4; j++) acc[i][j] = 0.f;

    for (int k0 = 0; k0 < K; k0 += BK) {
        int gr = bm0 + aRow;
        float4 av = (gr < M) ? *(const float4*)(A + (size_t)gr * K + k0 + aCol4)
                             : make_float4(0.f, 0.f, 0.f, 0.f);
        As[aCol4 + 0][aRow] = av.x;
        As[aCol4 + 1][aRow] = av.y;
        As[aCol4 + 2][aRow] = av.z;
        As[aCol4 + 3][aRow] = av.w;

        float4 bv = *(const float4*)(B + (size_t)(k0 + bRow) * N + bn0 + bCol4);
        *(float4*)&Bs[bRow][bCol4] = bv;

        __syncthreads();
#pragma unroll
        for (int kk = 0; kk < BK; kk++) {
            float4 a4 = *(const float4*)&As[kk][ty << 2];
            float4 b4 = *(const float4*)&Bs[kk][tx << 2];
            float ar[4] = {a4.x, a4.y, a4.z, a4.w};
            float br[4] = {b4.x, b4.y, b4.z, b4.w};
#pragma unroll
            for (int i = 0; i < 4; i++)
#pragma unroll
                for (int j = 0; j < 4; j++) acc[i][j] += ar[i] * br[j];
        }
        __syncthreads();
    }

#pragma unroll
    for (int i = 0; i < 4; i++) {
        int r = bm0 + (ty << 2) + i;
        if (r >= M) continue;
#pragma unroll
        for (int j = 0; j < 4; j++) {
            int col = bn0 + (tx << 2) + j;
            float v = acc[i][j];
            if (bias) v += bias[col];
            if (relu) v = fmaxf(v, 0.f);
            if (res) v += res[(size_t)r * N + col];
            C[(size_t)r * N + col] = v;
        }
    }
}

// ---------------- scatter kernels (D/4 threads per edge, float4 chunks) ----------
// plain: agg[dst] += x[src]
__global__ void scatter_add_kernel(const float* __restrict__ xext, int xSel,
                                   const int* __restrict__ src, const int* __restrict__ dst,
                                   int aggSel, int D4, int D, int total) {
    int tid = blockIdx.x * blockDim.x + threadIdx.x;
    if (tid >= total) return;
    const float* x = xext ? xext : scratch(xSel);
    float* agg = scratch(aggSel);
    int e = tid / D4;
    int c = (tid - e * D4) << 2;
    int s = src[e], d = dst[e];
    float4 v = *(const float4*)(x + (size_t)s * D + c);
    float* a = agg + (size_t)d * D + c;
    atomicAdd(a + 0, v.x); atomicAdd(a + 1, v.y);
    atomicAdd(a + 2, v.z); atomicAdd(a + 3, v.w);
}

// mpnn gather with fused pe3 concat: agg[dst] += x[src] + pe[src][c%64]  (D=192)
__global__ void scatter_add_pe_kernel(int xSel, const float* __restrict__ pe,
                                      const int* __restrict__ src, const int* __restrict__ dst,
                                      int aggSel, int total) {
    int tid = blockIdx.x * blockDim.x + threadIdx.x;
    if (tid >= total) return;
    const float* x = scratch(xSel);
    float* agg = scratch(aggSel);
    int e = tid / 48;
    int c = (tid - e * 48) << 2;
    int s = src[e], d = dst[e];
    float4 v = *(const float4*)(x + (size_t)s * 192 + c);
    float4 p = *(const float4*)(pe + (size_t)s * 64 + (c & 63));
    float* a = agg + (size_t)d * 192 + c;
    atomicAdd(a + 0, v.x + p.x); atomicAdd(a + 1, v.y + p.y);
    atomicAdd(a + 2, v.z + p.z); atomicAdd(a + 3, v.w + p.w);
}

// gcn: agg[dst] += hw[src] * dinv[src]*dinv[dst]   (D=192)
__global__ void scatter_gcn_kernel(int hwSel,
                                   const int* __restrict__ src, const int* __restrict__ dst,
                                   int aggSel, int total) {
    int tid = blockIdx.x * blockDim.x + threadIdx.x;
    if (tid >= total) return;
    const float* hw = scratch(hwSel);
    float* agg = scratch(aggSel);
    int e = tid / 48;
    int c = (tid - e * 48) << 2;
    int s = src[e], d = dst[e];
    float w = g_dinv[s] * g_dinv[d];
    float4 v = *(const float4*)(hw + (size_t)s * 192 + c);
    float* a = agg + (size_t)d * 192 + c;
    atomicAdd(a + 0, v.x * w); atomicAdd(a + 1, v.y * w);
    atomicAdd(a + 2, v.z * w); atomicAdd(a + 3, v.w * w);
}

// gcn with broadcast source feature hw = zgw[batch[src]]   (D=192)
__global__ void scatter_gcn_bcast_kernel(int zgwSel, const int* __restrict__ batch,
                                         const int* __restrict__ src, const int* __restrict__ dst,
                                         int aggSel, int total) {
    int tid = blockIdx.x * blockDim.x + threadIdx.x;
    if (tid >= total) return;
    const float* zgw = scratch(zgwSel);
    float* agg = scratch(aggSel);
    int e = tid / 48;
    int c = (tid - e * 48) << 2;
    int s = src[e], d = dst[e];
    float w = g_dinv[s] * g_dinv[d];
    float4 v = *(const float4*)(zgw + (size_t)batch[s] * 192 + c);
    float* a = agg + (size_t)d * 192 + c;
    atomicAdd(a + 0, v.x * w); atomicAdd(a + 1, v.y * w);
    atomicAdd(a + 2, v.z * w); atomicAdd(a + 3, v.w * w);
}

// gcn epilogue: out = relu(agg + hw*dinv^2 + b)   (D=192)
__global__ void gcn_epi_kernel(int aggSel, int hwSel, const float* __restrict__ b,
                               int outSel, int total) {
    int idx = blockIdx.x * blockDim.x + threadIdx.x;
    if (idx >= total) return;
    int i = idx / 192, f = idx - i * 192;
    float di = g_dinv[i];
    scratch(outSel)[idx] =
        fmaxf(scratch(aggSel)[idx] + scratch(hwSel)[idx] * di * di + b[f], 0.f);
}

__global__ void gcn_epi_bcast_kernel(int aggSel, int zgwSel, const int* __restrict__ batch,
                                     const float* __restrict__ b, int outSel, int total) {
    int idx = blockIdx.x * blockDim.x + threadIdx.x;
    if (idx >= total) return;
    int i = idx / 192, f = idx - i * 192;
    float di = g_dinv[i];
    scratch(outSel)[idx] =
        fmaxf(scratch(aggSel)[idx] +
              scratch(zgwSel)[(size_t)batch[i] * 192 + f] * di * di + b[f], 0.f);
}

// ---------------- attention (segment softmax over batch) ----------------
__device__ __forceinline__ void atomicMaxF(float* addr, float v) {
    if (v >= 0.f) atomicMax((int*)addr, __float_as_int(v));
    else          atomicMin((unsigned int*)addr, __float_as_uint(v));
}

__global__ void att_max_kernel(int gateSel, const int* __restrict__ batch, int total) {
    int idx = blockIdx.x * blockDim.x + threadIdx.x;
    if (idx >= total) return;
    int i = idx / 192, f = idx - i * 192;
    atomicMaxF(&scratch(SEL_GMAX)[batch[i] * 192 + f], scratch(gateSel)[idx]);
}

__global__ void att_exp_kernel(int gateSel, const int* __restrict__ batch, int total) {
    int idx = blockIdx.x * blockDim.x + threadIdx.x;
    if (idx >= total) return;
    int i = idx / 192, f = idx - i * 192;
    float* gate = scratch(gateSel);
    float e = expf(gate[idx] - scratch(SEL_GMAX)[batch[i] * 192 + f]);
    gate[idx] = e;
    atomicAdd(&scratch(SEL_ESUM)[batch[i] * 192 + f], e);
}

__global__ void att_zg_kernel(int gateSel, int zSel, const int* __restrict__ batch, int total) {
    int idx = blockIdx.x * blockDim.x + threadIdx.x;
    if (idx >= total) return;
    int i = idx / 192, f = idx - i * 192;
    int bf = batch[i] * 192 + f;
    atomicAdd(&scratch(SEL_ZG)[bf],
              scratch(gateSel)[idx] * scratch(zSel)[idx] / scratch(SEL_ESUM)[bf]);
}

// ---------------- launch helpers ----------------
static inline void launch_fill(int sel, float v, int n) {
    int n4 = n >> 2;
    fill_kernel<<<(n4 + 255) / 256, 256>>>(sel, v, n4);
}
static inline void launch_gemm(int M, int N, int K,
                               const float* Aext, int Asel, const float* B,
                               const float* bias, int resSel,
                               float* Cext, int Csel, int relu) {
    dim3 grid((N + 63) / 64, (M + 63) / 64);
    sgemm_kernel<<<grid, 256>>>(M, N, K, Aext, Asel, B, bias, resSel, Cext, Csel, relu);
}

extern "C" void kernel_launch(void* const* d_in, const int* in_sizes, int n_in,
                              void* d_out, int out_size) {
    const float* x1    = (const float*)d_in[0];
    const float* x2    = (const float*)d_in[1];
    const float* pe    = (const float*)d_in[2];
    const int*   ei    = (const int*)d_in[3];
    const int*   batch = (const int*)d_in[4];
    const float *Wc  = (const float*)d_in[5],  *bc  = (const float*)d_in[6];
    const float *Wmf = (const float*)d_in[7],  *bmf = (const float*)d_in[8];
    const float *Wgf = (const float*)d_in[9],  *bgf = (const float*)d_in[10];
    const float *Wmc = (const float*)d_in[11], *bmc = (const float*)d_in[12];
    const float *Wgc = (const float*)d_in[13], *bgc = (const float*)d_in[14];
    const float *Wa1 = (const float*)d_in[15], *ba1 = (const float*)d_in[16];
    const float *Wa2 = (const float*)d_in[17], *ba2 = (const float*)d_in[18];
    const float *Wgd = (const float*)d_in[19], *bgd = (const float*)d_in[20];
    const float *Wd1 = (const float*)d_in[21], *bd1 = (const float*)d_in[22];
    const float *Wd2 = (const float*)d_in[23], *bd2 = (const float*)d_in[24];
    const float *Wd3 = (const float*)d_in[25], *bd3 = (const float*)d_in[26];
    float* out = (float*)d_out;

    const int* src = ei;
    const int* dst = ei + NE;

    const int EDGE192 = NE * 48;
    const int EDGE32  = NE * 8;
    const int N192    = NN * 192;
    const int BLK = 256;

    // ---- degrees (shared by all GCN layers) ----
    deg_zero_kernel<<<(NN + BLK - 1) / BLK, BLK>>>();
    deg_kernel<<<(NE + BLK - 1) / BLK, BLK>>>(dst);
    dinv_kernel<<<(NN + BLK - 1) / BLK, BLK>>>();

    // ---- encoder ----
    // B0: x1_res = relu(x1 @ Wc + bc)
    launch_gemm(NN, 192, 384, x1, -1, Wc, bc, -1, nullptr, 0, 1);
    // B1 = scatter(x1_res + pe3); B2: h = relu(B1 @ Wmf + bmf)
    launch_fill(1, 0.f, N192);
    scatter_add_pe_kernel<<<(EDGE192 + BLK - 1) / BLK, BLK>>>(0, pe, src, dst, 1, EDGE192);
    launch_gemm(NN, 256, 192, nullptr, 1, Wmf, bmf, -1, nullptr, 2, 1);
    // B3: hw = h @ Wgf; B4: h2 = relu(gcn)
    launch_gemm(NN, 192, 256, nullptr, 2, Wgf, nullptr, -1, nullptr, 3, 0);
    launch_fill(1, 0.f, N192);
    scatter_gcn_kernel<<<(EDGE192 + BLK - 1) / BLK, BLK>>>(3, src, dst, 1, EDGE192);
    gcn_epi_kernel<<<(N192 + BLK - 1) / BLK, BLK>>>(1, 3, bgf, 4, N192);
    // B2: c = relu(mpnn(x2) @ Wmc + bmc)   (h dead)
    launch_fill(1, 0.f, NN * 32);
    scatter_add_kernel<<<(EDGE32 + BLK - 1) / BLK, BLK>>>(x2, -1, src, dst, 1, 8, 32, EDGE32);
    launch_gemm(NN, 64, 32, nullptr, 1, Wmc, bmc, -1, nullptr, 2, 1);
    // B3: hw = c @ Wgc; B5: c2 = relu(gcn)
    launch_gemm(NN, 192, 64, nullptr, 2, Wgc, nullptr, -1, nullptr, 3, 0);
    launch_fill(1, 0.f, N192);
    scatter_gcn_kernel<<<(EDGE192 + BLK - 1) / BLK, BLK>>>(3, src, dst, 1, EDGE192);
    gcn_epi_kernel<<<(N192 + BLK - 1) / BLK, BLK>>>(1, 3, bgc, 5, N192);
    // B4: z = h2 + c2 + x1_res   (in-place over h2)
    add3_kernel<<<(N192 + BLK - 1) / BLK, BLK>>>(4, 5, 0, 4, N192);

    // ---- attentional aggregation ----
    // B2: tmp = relu(z @ Wa1 + ba1); B3: gate = tmp @ Wa2 + ba2
    launch_gemm(NN, 256, 192, nullptr, 4, Wa1, ba1, -1, nullptr, 2, 1);
    launch_gemm(NN, 192, 256, nullptr, 2, Wa2, ba2, -1, nullptr, 3, 0);
    launch_fill(SEL_GMAX, -FLT_MAX, NG * 192);
    launch_fill(SEL_ESUM, 0.f, NG * 192);
    launch_fill(SEL_ZG,   0.f, NG * 192);
    att_max_kernel<<<(N192 + BLK - 1) / BLK, BLK>>>(3, batch, N192);
    att_exp_kernel<<<(N192 + BLK - 1) / BLK, BLK>>>(3, batch, N192);
    att_zg_kernel<<<(N192 + BLK - 1) / BLK, BLK>>>(3, 4, batch, N192);

    // ---- decoder ----
    // zgw = zg @ Wgd  (64x192x192 — tiny); gather in scatter (z1@Wgd commutes with gather)
    launch_gemm(NG, 192, 192, nullptr, SEL_ZG, Wgd, nullptr, -1, nullptr, SEL_ZGW, 0);
    launch_fill(1, 0.f, N192);
    scatter_gcn_bcast_kernel<<<(EDGE192 + BLK - 1) / BLK, BLK>>>(SEL_ZGW, batch, src, dst, 1, EDGE192);
    gcn_epi_bcast_kernel<<<(N192 + BLK - 1) / BLK, BLK>>>(1, SEL_ZGW, batch, bgd, 5, N192);
    // B2: t = relu(mpnn(z1_res + pe3) @ Wd1 + bd1)
    launch_fill(1, 0.f, N192);
    scatter_add_pe_kernel<<<(EDGE192 + BLK - 1) / BLK, BLK>>>(5, pe, src, dst, 1, EDGE192);
    launch_gemm(NN, 192, 192, nullptr, 1, Wd1, bd1, -1, nullptr, 2, 1);
    // B3: t2 = relu(mpnn(t) @ Wd2 + bd2) + z1_res
    launch_fill(1, 0.f, N192);
    scatter_add_kernel<<<(EDGE192 + BLK - 1) / BLK, BLK>>>(nullptr, 2, src, dst, 1, 48, 192, EDGE192);
    launch_gemm(NN, 192, 192, nullptr, 1, Wd2, bd2, 5, nullptr, 3, 1);
    // out = relu(mpnn(t2) @ Wd3 + bd3)
    launch_fill(1, 0.f, N192);
    scatter_add_kernel<<<(EDGE192 + BLK - 1) / BLK, BLK>>>(nullptr, 3, src, dst, 1, 48, 192, EDGE192);
    launch_gemm(NN, 384, 192, nullptr, 1, Wd3, bd3, -1, out, -1, 1);
}

// round 3
// speedup vs baseline: 1.7036x; 1.7036x over previous
#include <cuda_runtime.h>
#include <math.h>
#include <float.h>

#define NN 100000
#define NE 800000
#define NG 64

// ---------------- scratch pool (device globals; resolved device-side) ----------------
__device__ float g_B0[NN * 192];   // x1_res
__device__ float g_B1[NN * 192];   // agg (mpnn gather target)
__device__ float g_B2[NN * 256];   // h -> c -> tmp -> t
__device__ float g_B3[NN * 192];   // hw -> gate -> t2
__device__ float g_B4[NN * 192];   // h2 -> z
__device__ float g_B5[NN * 192];   // c2 -> z1_res
__device__ float g_dinv[NN];
__device__ float g_small[4 * NG * 192];  // zg | gmax | esum | zgw
__device__ int   g_rowptr[NN + 1];
__device__ int   g_pos[NN];              // int degree, then fill cursor
__device__ int   g_csrc[NE];             // edge sources sorted by dst (CSR)

#define SEL_ZG   16
#define SEL_GMAX 17
#define SEL_ESUM 18
#define SEL_ZGW  19

__device__ __forceinline__ float* scratch(int id) {
    switch (id) {
        case 0:  return g_B0;
        case 1:  return g_B1;
        case 2:  return g_B2;
        case 3:  return g_B3;
        case 4:  return g_B4;
        case 5:  return g_B5;
        case SEL_ZG:   return g_small;
        case SEL_GMAX: return g_small + NG * 192;
        case SEL_ESUM: return g_small + 2 * NG * 192;
        case SEL_ZGW:  return g_small + 3 * NG * 192;
        default: return nullptr;
    }
}

// ---------------- CSR build ----------------
__global__ void zero_pos_kernel() {
    int i = blockIdx.x * blockDim.x + threadIdx.x;
    if (i < NN) g_pos[i] = 0;
}

__global__ void count_deg_kernel(const int* __restrict__ dst) {
    int e = blockIdx.x * blockDim.x + threadIdx.x;
    if (e < NE) atomicAdd(&g_pos[dst[e]], 1);
}

__global__ void dinv_kernel() {
    int i = blockIdx.x * blockDim.x + threadIdx.x;
    if (i < NN) g_dinv[i] = rsqrtf((float)g_pos[i] + 1.0f);
}

// single-block exclusive scan of g_pos -> g_rowptr (and reset g_pos to row start)
__global__ void scan_kernel() {
    __shared__ int s[1024];
    __shared__ int carry;
    int tid = threadIdx.x;
    if (tid == 0) carry = 0;
    __syncthreads();
    for (int base = 0; base < NN; base += 1024) {
        int idx = base + tid;
        int v = (idx < NN) ? g_pos[idx] : 0;
        s[tid] = v;
        __syncthreads();
        for (int off = 1; off < 1024; off <<= 1) {
            int t = (tid >= off) ? s[tid - off] : 0;
            __syncthreads();
            s[tid] += t;
            __syncthreads();
        }
        int incl = s[tid];
        int c = carry;
        if (idx < NN) {
            int excl = c + incl - v;
            g_rowptr[idx] = excl;
            g_pos[idx] = excl;
        }
        __syncthreads();
        if (tid == 0) carry = c + s[1023];
        __syncthreads();
    }
    if (tid == 0) g_rowptr[NN] = carry;
}

__global__ void csr_fill_kernel(const int* __restrict__ src, const int* __restrict__ dst) {
    int e = blockIdx.x * blockDim.x + threadIdx.x;
    if (e >= NE) return;
    int p = atomicAdd(&g_pos[dst[e]], 1);
    g_csrc[p] = src[e];
}

// ---------------- small utility kernels ----------------
__global__ void fill_kernel(int sel, float v, int n4) {
    int i = blockIdx.x * blockDim.x + threadIdx.x;
    if (i < n4) ((float4*)scratch(sel))[i] = make_float4(v, v, v, v);
}

// o = a + b + c (elementwise)
__global__ void add3_kernel(int aSel, int bSel, int cSel, int oSel, int n) {
    int i = blockIdx.x * blockDim.x + threadIdx.x;
    if (i < n) {
        scratch(oSel)[i] = scratch(aSel)[i] + scratch(bSel)[i] + scratch(cSel)[i];
    }
}

// ---------------- gather kernels (CSR, no atomics) ----------------
// agg[i] = sum_{e in in(i)} x[src_e] (+ pe3[src_e])   ; D4 float4-chunks per node
__global__ void gather_add_kernel(const float* __restrict__ xext, int xSel,
                                  const float* __restrict__ pe,
                                  int aggSel, int D4, int D, int total) {
    int tid = blockIdx.x * blockDim.x + threadIdx.x;
    if (tid >= total) return;
    const float* x = xext ? xext : scratch(xSel);
    float* agg = scratch(aggSel);
    int i = tid / D4;
    int c = (tid - i * D4) << 2;
    int beg = g_rowptr[i], end = g_rowptr[i + 1];
    float4 acc = make_float4(0.f, 0.f, 0.f, 0.f);
    for (int e = beg; e < end; e++) {
        int s = g_csrc[e];
        float4 v = *(const float4*)(x + (size_t)s * D + c);
        if (pe) {
            float4 p = *(const float4*)(pe + (size_t)s * 64 + (c & 63));
            v.x += p.x; v.y += p.y; v.z += p.z; v.w += p.w;
        }
        acc.x += v.x; acc.y += v.y; acc.z += v.z; acc.w += v.w;
    }
    *(float4*)(agg + (size_t)i * D + c) = acc;
}

// fused GCN: out[i] = relu(dinv[i]*sum(hw[s]*dinv[s]) + hw[i]*dinv[i]^2 + b)  (D=192)
__global__ void gather_gcn_kernel(int hwSel, const float* __restrict__ b,
                                  int outSel, int total) {
    int tid = blockIdx.x * blockDim.x + threadIdx.x;
    if (tid >= total) return;
    const float* hw = scratch(hwSel);
    float* out = scratch(outSel);
    int i = tid / 48;
    int c = (tid - i * 48) << 2;
    int beg = g_rowptr[i], end = g_rowptr[i + 1];
    float4 acc = make_float4(0.f, 0.f, 0.f, 0.f);
    for (int e = beg; e < end; e++) {
        int s = g_csrc[e];
        float w = g_dinv[s];
        float4 v = *(const float4*)(hw + (size_t)s * 192 + c);
        acc.x += v.x * w; acc.y += v.y * w; acc.z += v.z * w; acc.w += v.w * w;
    }
    float di = g_dinv[i];
    float dii = di * di;
    float4 sv = *(const float4*)(hw + (size_t)i * 192 + c);
    float4 bb = *(const float4*)(b + c);
    float4 o;
    o.x = fmaxf(acc.x * di + sv.x * dii + bb.x, 0.f);
    o.y = fmaxf(acc.y * di + sv.y * dii + bb.y, 0.f);
    o.z = fmaxf(acc.z * di + sv.z * dii + bb.z, 0.f);
    o.w = fmaxf(acc.w * di + sv.w * dii + bb.w, 0.f);
    *(float4*)(out + (size_t)i * 192 + c) = o;
}

// fused GCN with broadcast source features hw[s] = zgw[batch[s]]  (D=192)
__global__ void gather_gcn_bcast_kernel(int zgwSel, const int* __restrict__ batch,
                                        const float* __restrict__ b,
                                        int outSel, int total) {
    int tid = blockIdx.x * blockDim.x + threadIdx.x;
    if (tid >= total) return;
    const float* zgw = scratch(zgwSel);
    float* out = scratch(outSel);
    int i = tid / 48;
    int c = (tid - i * 48) << 2;
    int beg = g_rowptr[i], end = g_rowptr[i + 1];
    float4 acc = make_float4(0.f, 0.f, 0.f, 0.f);
    for (int e = beg; e < end; e++) {
        int s = g_csrc[e];
        float w = g_dinv[s];
        float4 v = *(const float4*)(zgw + (size_t)batch[s] * 192 + c);
        acc.x += v.x * w; acc.y += v.y * w; acc.z += v.z * w; acc.w += v.w * w;
    }
    float di = g_dinv[i];
    float dii = di * di;
    float4 sv = *(const float4*)(zgw + (size_t)batch[i] * 192 + c);
    float4 bb = *(const float4*)(b + c);
    float4 o;
    o.x = fmaxf(acc.x * di + sv.x * dii + bb.x, 0.f);
    o.y = fmaxf(acc.y * di + sv.y * dii + bb.y, 0.f);
    o.z = fmaxf(acc.z * di + sv.z * dii + bb.z, 0.f);
    o.w = fmaxf(acc.w * di + sv.w * dii + bb.w, 0.f);
    *(float4*)(out + (size_t)i * 192 + c) = o;
}

// ---------------- SGEMM: C = act(A @ B + bias) (+res) ----------------
// BM=128, BN=64, BK=16, 256 threads, 8x4 micro-tile, prefetched global loads.
__global__ __launch_bounds__(256)
void sgemm_kernel(int M, int N, int K,
                  const float* __restrict__ Aext, int Asel,
                  const float* __restrict__ B,
                  const float* __restrict__ bias,
                  int resSel,
                  float* __restrict__ Cext, int Csel,
                  int relu) {
    __shared__ float As[16][128];
    __shared__ float Bs[16][64];

    const float* A = Aext ? Aext : scratch(Asel);
    float* C = Cext ? Cext : scratch(Csel);
    const float* res = (resSel >= 0) ? scratch(resSel) : nullptr;

    int tid = threadIdx.x;
    int bm0 = blockIdx.y * 128, bn0 = blockIdx.x * 64;
    int tx = tid & 15, ty = tid >> 4;
    int aRow = tid >> 1, aCol8 = (tid & 1) << 3;
    int bRow = tid >> 4, bCol4 = (tid & 15) << 2;

    const float* Aptr = A + (size_t)(bm0 + aRow) * K + aCol8;
    bool aValid = (bm0 + aRow) < M;
    const float* Bptr = B + (size_t)bRow * N + bn0 + bCol4;

    float acc[8][4];
#pragma unroll
    for (int i = 0; i < 8; i++)
#pragma unroll
        for (int j = 0; j < 4; j++) acc[i][j] = 0.f;

    float4 a0 = make_float4(0.f, 0.f, 0.f, 0.f), a1 = a0;
    if (aValid) {
        a0 = *(const float4*)(Aptr);
        a1 = *(const float4*)(Aptr + 4);
    }
    float4 bv = *(const float4*)(Bptr);

    for (int k0 = 0; k0 < K; k0 += 16) {
        As[aCol8 + 0][aRow] = a0.x; As[aCol8 + 1][aRow] = a0.y;
        As[aCol8 + 2][aRow] = a0.z; As[aCol8 + 3][aRow] = a0.w;
        As[aCol8 + 4][aRow] = a1.x; As[aCol8 + 5][aRow] = a1.y;
        As[aCol8 + 6][aRow] = a1.z; As[aCol8 + 7][aRow] = a1.w;
        *(float4*)&Bs[bRow][bCol4] = bv;
        __syncthreads();

        // prefetch next tile while computing this one
        if (k0 + 16 < K) {
            if (aValid) {
                a0 = *(const float4*)(Aptr + k0 + 16);
                a1 = *(const float4*)(Aptr + k0 + 20);
            }
            bv = *(const float4*)(Bptr + (size_t)(k0 + 16) * N);
        }

#pragma unroll
        for (int kk = 0; kk < 16; kk++) {
            float4 a0v = *(const float4*)&As[kk][ty << 3];
            float4 a1v = *(const float4*)&As[kk][(ty << 3) + 4];
            float4 b4 = *(const float4*)&Bs[kk][tx << 2];
            float ar[8] = {a0v.x, a0v.y, a0v.z, a0v.w, a1v.x, a1v.y, a1v.z, a1v.w};
            float br[4] = {b4.x, b4.y, b4.z, b4.w};
#pragma unroll
            for (int i = 0; i < 8; i++)
#pragma unroll
                for (int j = 0; j < 4; j++) acc[i][j] += ar[i] * br[j];
        }
        __syncthreads();
    }

    float4 b4 = bias ? *(const float4*)(bias + bn0 + (tx << 2))
                     : make_float4(0.f, 0.f, 0.f, 0.f);
    int col = bn0 + (tx << 2);
#pragma unroll
    for (int i = 0; i < 8; i++) {
        int r = bm0 + (ty << 3) + i;
        if (r >= M) continue;
        float4 v;
        v.x = acc[i][0] + b4.x; v.y = acc[i][1] + b4.y;
        v.z = acc[i][2] + b4.z; v.w = acc[i][3] + b4.w;
        if (relu) {
            v.x = fmaxf(v.x, 0.f); v.y = fmaxf(v.y, 0.f);
            v.z = fmaxf(v.z, 0.f); v.w = fmaxf(v.w, 0.f);
        }
        if (res) {
            float4 rv = *(const float4*)(res + (size_t)r * N + col);
            v.x += rv.x; v.y += rv.y; v.z += rv.z; v.w += rv.w;
        }
        *(float4*)(C + (size_t)r * N + col) = v;
    }
}

// ---------------- attention (segment softmax over batch) ----------------
__device__ __forceinline__ void atomicMaxF(float* addr, float v) {
    if (v >= 0.f) atomicMax((int*)addr, __float_as_int(v));
    else          atomicMin((unsigned int*)addr, __float_as_uint(v));
}

__global__ void att_max_kernel(int gateSel, const int* __restrict__ batch, int total) {
    int idx = blockIdx.x * blockDim.x + threadIdx.x;
    if (idx >= total) return;
    int i = idx / 192, f = idx - i * 192;
    atomicMaxF(&scratch(SEL_GMAX)[batch[i] * 192 + f], scratch(gateSel)[idx]);
}

__global__ void att_exp_kernel(int gateSel, const int* __restrict__ batch, int total) {
    int idx = blockIdx.x * blockDim.x + threadIdx.x;
    if (idx >= total) return;
    int i = idx / 192, f = idx - i * 192;
    float* gate = scratch(gateSel);
    float e = expf(gate[idx] - scratch(SEL_GMAX)[batch[i] * 192 + f]);
    gate[idx] = e;
    atomicAdd(&scratch(SEL_ESUM)[batch[i] * 192 + f], e);
}

__global__ void att_zg_kernel(int gateSel, int zSel, const int* __restrict__ batch, int total) {
    int idx = blockIdx.x * blockDim.x + threadIdx.x;
    if (idx >= total) return;
    int i = idx / 192, f = idx - i * 192;
    int bf = batch[i] * 192 + f;
    atomicAdd(&scratch(SEL_ZG)[bf],
              scratch(gateSel)[idx] * scratch(zSel)[idx] / scratch(SEL_ESUM)[bf]);
}

// ---------------- launch helpers ----------------
static inline void launch_fill(int sel, float v, int n) {
    int n4 = n >> 2;
    fill_kernel<<<(n4 + 255) / 256, 256>>>(sel, v, n4);
}
static inline void launch_gemm(int M, int N, int K,
                               const float* Aext, int Asel, const float* B,
                               const float* bias, int resSel,
                               float* Cext, int Csel, int relu) {
    dim3 grid((N + 63) / 64, (M + 127) / 128);
    sgemm_kernel<<<grid, 256>>>(M, N, K, Aext, Asel, B, bias, resSel, Cext, Csel, relu);
}

extern "C" void kernel_launch(void* const* d_in, const int* in_sizes, int n_in,
                              void* d_out, int out_size) {
    const float* x1    = (const float*)d_in[0];
    const float* x2    = (const float*)d_in[1];
    const float* pe    = (const float*)d_in[2];
    const int*   ei    = (const int*)d_in[3];
    const int*   batch = (const int*)d_in[4];
    const float *Wc  = (const float*)d_in[5],  *bc  = (const float*)d_in[6];
    const float *Wmf = (const float*)d_in[7],  *bmf = (const float*)d_in[8];
    const float *Wgf = (const float*)d_in[9],  *bgf = (const float*)d_in[10];
    const float *Wmc = (const float*)d_in[11], *bmc = (const float*)d_in[12];
    const float *Wgc = (const float*)d_in[13], *bgc = (const float*)d_in[14];
    const float *Wa1 = (const float*)d_in[15], *ba1 = (const float*)d_in[16];
    const float *Wa2 = (const float*)d_in[17], *ba2 = (const float*)d_in[18];
    const float *Wgd = (const float*)d_in[19], *bgd = (const float*)d_in[20];
    const float *Wd1 = (const float*)d_in[21], *bd1 = (const float*)d_in[22];
    const float *Wd2 = (const float*)d_in[23], *bd2 = (const float*)d_in[24];
    const float *Wd3 = (const float*)d_in[25], *bd3 = (const float*)d_in[26];
    float* out = (float*)d_out;

    const int* src = ei;
    const int* dst = ei + NE;

    const int NODE192 = NN * 48;   // threads for D=192 gathers
    const int NODE32  = NN * 8;    // threads for D=32 gather
    const int N192    = NN * 192;
    const int BLK = 256;

    // ---- CSR build (once; reused by all 8 aggregations) ----
    zero_pos_kernel<<<(NN + BLK - 1) / BLK, BLK>>>();
    count_deg_kernel<<<(NE + BLK - 1) / BLK, BLK>>>(dst);
    dinv_kernel<<<(NN + BLK - 1) / BLK, BLK>>>();
    scan_kernel<<<1, 1024>>>();
    csr_fill_kernel<<<(NE + BLK - 1) / BLK, BLK>>>(src, dst);

    // ---- encoder ----
    // B0: x1_res = relu(x1 @ Wc + bc)
    launch_gemm(NN, 192, 384, x1, -1, Wc, bc, -1, nullptr, 0, 1);
    // B1 = gather(x1_res + pe3); B2: h = relu(B1 @ Wmf + bmf)
    gather_add_kernel<<<(NODE192 + BLK - 1) / BLK, BLK>>>(nullptr, 0, pe, 1, 48, 192, NODE192);
    launch_gemm(NN, 256, 192, nullptr, 1, Wmf, bmf, -1, nullptr, 2, 1);
    // B3: hw = h @ Wgf; B4: h2 = relu(gcn)  [fused gather+epilogue]
    launch_gemm(NN, 192, 256, nullptr, 2, Wgf, nullptr, -1, nullptr, 3, 0);
    gather_gcn_kernel<<<(NODE192 + BLK - 1) / BLK, BLK>>>(3, bgf, 4, NODE192);
    // B1 = gather(x2); B2: c = relu(B1 @ Wmc + bmc)
    gather_add_kernel<<<(NODE32 + BLK - 1) / BLK, BLK>>>(x2, -1, nullptr, 1, 8, 32, NODE32);
    launch_gemm(NN, 64, 32, nullptr, 1, Wmc, bmc, -1, nullptr, 2, 1);
    // B3: hw = c @ Wgc; B5: c2 = relu(gcn)
    launch_gemm(NN, 192, 64, nullptr, 2, Wgc, nullptr, -1, nullptr, 3, 0);
    gather_gcn_kernel<<<(NODE192 + BLK - 1) / BLK, BLK>>>(3, bgc, 5, NODE192);
    // B4: z = h2 + c2 + x1_res
    add3_kernel<<<(N192 + BLK - 1) / BLK, BLK>>>(4, 5, 0, 4, N192);

    // ---- attentional aggregation ----
    launch_gemm(NN, 256, 192, nullptr, 4, Wa1, ba1, -1, nullptr, 2, 1);
    launch_gemm(NN, 192, 256, nullptr, 2, Wa2, ba2, -1, nullptr, 3, 0);
    launch_fill(SEL_GMAX, -FLT_MAX, NG * 192);
    launch_fill(SEL_ESUM, 0.f, NG * 192);
    launch_fill(SEL_ZG,   0.f, NG * 192);
    att_max_kernel<<<(N192 + BLK - 1) / BLK, BLK>>>(3, batch, N192);
    att_exp_kernel<<<(N192 + BLK - 1) / BLK, BLK>>>(3, batch, N192);
    att_zg_kernel<<<(N192 + BLK - 1) / BLK, BLK>>>(3, 4, batch, N192);

    // ---- decoder ----
    // zgw = zg @ Wgd (tiny); fused bcast gather+epilogue -> B5 (z1_res)
    launch_gemm(NG, 192, 192, nullptr, SEL_ZG, Wgd, nullptr, -1, nullptr, SEL_ZGW, 0);
    gather_gcn_bcast_kernel<<<(NODE192 + BLK - 1) / BLK, BLK>>>(SEL_ZGW, batch, bgd, 5, NODE192);
    // B1 = gather(z1_res + pe3); B2: t = relu(B1 @ Wd1 + bd1)
    gather_add_kernel<<<(NODE192 + BLK - 1) / BLK, BLK>>>(nullptr, 5, pe, 1, 48, 192, NODE192);
    launch_gemm(NN, 192, 192, nullptr, 1, Wd1, bd1, -1, nullptr, 2, 1);
    // B1 = gather(t); B3: t2 = relu(B1 @ Wd2 + bd2) + z1_res
    gather_add_kernel<<<(NODE192 + BLK - 1) / BLK, BLK>>>(nullptr, 2, nullptr, 1, 48, 192, NODE192);
    launch_gemm(NN, 192, 192, nullptr, 1, Wd2, bd2, 5, nullptr, 3, 1);
    // B1 = gather(t2); out = relu(B1 @ Wd3 + bd3)
    gather_add_kernel<<<(NODE192 + BLK - 1) / BLK, BLK>>>(nullptr, 3, nullptr, 1, 48, 192, NODE192);
    launch_gemm(NN, 384, 192, nullptr, 1, Wd3, bd3, -1, out, -1, 1);
}

// round 4
// speedup vs baseline: 2.2521x; 1.3220x over previous
#include <cuda_runtime.h>
#include <math.h>
#include <float.h>
#include <stdint.h>

#define NN 100000
#define NE 800000
#define NG 64
#define NSCAN_BLK 98   // ceil(NN/1024)

// ---------------- scratch pool (device globals; resolved device-side) ----------------
__device__ float g_B0[NN * 192];   // x1_res
__device__ float g_B1[NN * 192];   // agg (gather target)
__device__ float g_B2[NN * 256];   // h -> c -> tmp -> t
__device__ float g_B3[NN * 192];   // hw -> gate -> t2
__device__ float g_B4[NN * 192];   // h2 -> z
__device__ float g_B5[NN * 192];   // c2 -> z1_res
__device__ float g_dinv[NN];
__device__ float g_small[4 * NG * 192];  // zg | gmax | esum | zgw
__device__ int   g_rowptr[NN + 1];
__device__ int   g_pos[NN];
__device__ int   g_bsum[128];
__device__ int   g_csrc[NE];

#define SEL_ZG   16
#define SEL_GMAX 17
#define SEL_ESUM 18
#define SEL_ZGW  19

__device__ __forceinline__ float* scratch(int id) {
    switch (id) {
        case 0:  return g_B0;
        case 1:  return g_B1;
        case 2:  return g_B2;
        case 3:  return g_B3;
        case 4:  return g_B4;
        case 5:  return g_B5;
        case SEL_ZG:   return g_small;
        case SEL_GMAX: return g_small + NG * 192;
        case SEL_ESUM: return g_small + 2 * NG * 192;
        case SEL_ZGW:  return g_small + 3 * NG * 192;
        default: return nullptr;
    }
}

// ---------------- CSR build ----------------
__global__ void zero_pos_kernel() {
    int i = blockIdx.x * blockDim.x + threadIdx.x;
    if (i < NN) g_pos[i] = 0;
}

__global__ void count_deg_kernel(const int* __restrict__ dst) {
    int e = blockIdx.x * blockDim.x + threadIdx.x;
    if (e < NE) atomicAdd(&g_pos[dst[e]], 1);
}

__global__ void dinv_kernel() {
    int i = blockIdx.x * blockDim.x + threadIdx.x;
    if (i < NN) g_dinv[i] = rsqrtf((float)g_pos[i] + 1.0f);
}

// multi-block scan: local exclusive + block sums
__global__ void scan1_kernel() {
    __shared__ int s[1024];
    int tid = threadIdx.x;
    int idx = blockIdx.x * 1024 + tid;
    int v = (idx < NN) ? g_pos[idx] : 0;
    s[tid] = v;
    __syncthreads();
    for (int off = 1; off < 1024; off <<= 1) {
        int t = (tid >= off) ? s[tid - off] : 0;
        __syncthreads();
        s[tid] += t;
        __syncthreads();
    }
    if (idx < NN) g_rowptr[idx] = s[tid] - v;
    if (tid == 1023) g_bsum[blockIdx.x] = s[1023];
}

__global__ void scan2_kernel() {
    __shared__ int s[128];
    int tid = threadIdx.x;
    int v = (tid < NSCAN_BLK) ? g_bsum[tid] : 0;
    s[tid] = v;
    __syncthreads();
    for (int off = 1; off < 128; off <<= 1) {
        int t = (tid >= off) ? s[tid - off] : 0;
        __syncthreads();
        s[tid] += t;
        __syncthreads();
    }
    if (tid < NSCAN_BLK) g_bsum[tid] = s[tid] - v;
    if (tid == 127) g_rowptr[NN] = s[127];
}

__global__ void scan3_kernel() {
    int idx = blockIdx.x * 1024 + threadIdx.x;
    if (idx < NN) {
        int r = g_rowptr[idx] + g_bsum[blockIdx.x];
        g_rowptr[idx] = r;
        g_pos[idx] = r;
    }
}

__global__ void csr_fill_kernel(const int* __restrict__ src, const int* __restrict__ dst) {
    int e = blockIdx.x * blockDim.x + threadIdx.x;
    if (e >= NE) return;
    int p = atomicAdd(&g_pos[dst[e]], 1);
    g_csrc[p] = src[e];
}

// ---------------- small utility kernels ----------------
__global__ void fill_kernel(int sel, float v, int n4) {
    int i = blockIdx.x * blockDim.x + threadIdx.x;
    if (i < n4) ((float4*)scratch(sel))[i] = make_float4(v, v, v, v);
}

__global__ void add3_kernel(int aSel, int bSel, int cSel, int oSel, int n) {
    int i = blockIdx.x * blockDim.x + threadIdx.x;
    if (i < n) {
        scratch(oSel)[i] = scratch(aSel)[i] + scratch(bSel)[i] + scratch(cSel)[i];
    }
}

// ---------------- gather kernels (CSR, no atomics) ----------------
__global__ void gather_add_kernel(const float* __restrict__ xext, int xSel,
                                  const float* __restrict__ pe,
                                  int aggSel, int D4, int D, int total) {
    int tid = blockIdx.x * blockDim.x + threadIdx.x;
    if (tid >= total) return;
    const float* x = xext ? xext : scratch(xSel);
    float* agg = scratch(aggSel);
    int i = tid / D4;
    int c = (tid - i * D4) << 2;
    int beg = g_rowptr[i], end = g_rowptr[i + 1];
    float4 acc = make_float4(0.f, 0.f, 0.f, 0.f);
    for (int e = beg; e < end; e++) {
        int s = g_csrc[e];
        float4 v = *(const float4*)(x + (size_t)s * D + c);
        if (pe) {
            float4 p = *(const float4*)(pe + (size_t)s * 64 + (c & 63));
            v.x += p.x; v.y += p.y; v.z += p.z; v.w += p.w;
        }
        acc.x += v.x; acc.y += v.y; acc.z += v.z; acc.w += v.w;
    }
    *(float4*)(agg + (size_t)i * D + c) = acc;
}

__global__ void gather_gcn_kernel(int hwSel, const float* __restrict__ b,
                                  int outSel, int total) {
    int tid = blockIdx.x * blockDim.x + threadIdx.x;
    if (tid >= total) return;
    const float* hw = scratch(hwSel);
    float* out = scratch(outSel);
    int i = tid / 48;
    int c = (tid - i * 48) << 2;
    int beg = g_rowptr[i], end = g_rowptr[i + 1];
    float4 acc = make_float4(0.f, 0.f, 0.f, 0.f);
    for (int e = beg; e < end; e++) {
        int s = g_csrc[e];
        float w = g_dinv[s];
        float4 v = *(const float4*)(hw + (size_t)s * 192 + c);
        acc.x += v.x * w; acc.y += v.y * w; acc.z += v.z * w; acc.w += v.w * w;
    }
    float di = g_dinv[i];
    float dii = di * di;
    float4 sv = *(const float4*)(hw + (size_t)i * 192 + c);
    float4 bb = *(const float4*)(b + c);
    float4 o;
    o.x = fmaxf(acc.x * di + sv.x * dii + bb.x, 0.f);
    o.y = fmaxf(acc.y * di + sv.y * dii + bb.y, 0.f);
    o.z = fmaxf(acc.z * di + sv.z * dii + bb.z, 0.f);
    o.w = fmaxf(acc.w * di + sv.w * dii + bb.w, 0.f);
    *(float4*)(out + (size_t)i * 192 + c) = o;
}

__global__ void gather_gcn_bcast_kernel(int zgwSel, const int* __restrict__ batch,
                                        const float* __restrict__ b,
                                        int outSel, int total) {
    int tid = blockIdx.x * blockDim.x + threadIdx.x;
    if (tid >= total) return;
    const float* zgw = scratch(zgwSel);
    float* out = scratch(outSel);
    int i = tid / 48;
    int c = (tid - i * 48) << 2;
    int beg = g_rowptr[i], end = g_rowptr[i + 1];
    float4 acc = make_float4(0.f, 0.f, 0.f, 0.f);
    for (int e = beg; e < end; e++) {
        int s = g_csrc[e];
        float w = g_dinv[s];
        float4 v = *(const float4*)(zgw + (size_t)batch[s] * 192 + c);
        acc.x += v.x * w; acc.y += v.y * w; acc.z += v.z * w; acc.w += v.w * w;
    }
    float di = g_dinv[i];
    float dii = di * di;
    float4 sv = *(const float4*)(zgw + (size_t)batch[i] * 192 + c);
    float4 bb = *(const float4*)(b + c);
    float4 o;
    o.x = fmaxf(acc.x * di + sv.x * dii + bb.x, 0.f);
    o.y = fmaxf(acc.y * di + sv.y * dii + bb.y, 0.f);
    o.z = fmaxf(acc.z * di + sv.z * dii + bb.z, 0.f);
    o.w = fmaxf(acc.w * di + sv.w * dii + bb.w, 0.f);
    *(float4*)(out + (size_t)i * 192 + c) = o;
}

// ---------------- TF32 tensor-core GEMM ----------------
// C[M,N] = act(A[M,K] @ B[K,N] + bias) (+res). BM=128, BN=64, BK=16.
// 8 warps, each 32x32; mma.sync.m16n8k8 tf32, RN conversion at smem store.
__device__ __forceinline__ uint32_t f2tf(float f) {
    uint32_t u;
    asm("cvt.rna.tf32.f32 %0, %1;" : "=r"(u) : "f"(f));
    return u;
}

__device__ __forceinline__ void mma_tf32(float& c0, float& c1, float& c2, float& c3,
                                         uint32_t a0, uint32_t a1, uint32_t a2, uint32_t a3,
                                         uint32_t b0, uint32_t b1) {
    asm volatile(
        "mma.sync.aligned.m16n8k8.row.col.f32.tf32.tf32.f32 "
        "{%0,%1,%2,%3},{%4,%5,%6,%7},{%8,%9},{%0,%1,%2,%3};\n"
        : "+f"(c0), "+f"(c1), "+f"(c2), "+f"(c3)
        : "r"(a0), "r"(a1), "r"(a2), "r"(a3), "r"(b0), "r"(b1));
}

__global__ __launch_bounds__(256)
void tgemm_kernel(int M, int N, int K,
                  const float* __restrict__ Aext, int Asel,
                  const float* __restrict__ B,
                  const float* __restrict__ bias,
                  int resSel,
                  float* __restrict__ Cext, int Csel,
                  int relu) {
    __shared__ uint32_t As[128][20];  // row-major [m][k], pad->stride 20 (conflict-free frags)
    __shared__ uint32_t Bs[16][72];   // [k][n], pad->stride 72 (conflict-free frags)

    const float* A = Aext ? Aext : scratch(Asel);
    float* C = Cext ? Cext : scratch(Csel);
    const float* res = (resSel >= 0) ? scratch(resSel) : nullptr;

    int tid = threadIdx.x;
    int bm0 = blockIdx.y * 128, bn0 = blockIdx.x * 64;
    int lane = tid & 31;
    int wid = tid >> 5;
    int g = lane >> 2, t4 = lane & 3;
    int wm = (wid & 3) * 32;    // warp m-offset
    int wn = (wid >> 2) * 32;   // warp n-offset

    int aRow = tid >> 1, aCol = (tid & 1) << 3;    // 128x16, 8 floats/thread
    int bRow = tid >> 4, bCol = (tid & 15) << 2;   // 16x64, 4 floats/thread

    const float* Aptr = A + (size_t)(bm0 + aRow) * K + aCol;
    bool aValid = (bm0 + aRow) < M;
    const float* Bptr = B + (size_t)bRow * N + bn0 + bCol;

    float acc[2][4][4];
#pragma unroll
    for (int mi = 0; mi < 2; mi++)
#pragma unroll
        for (int ni = 0; ni < 4; ni++)
#pragma unroll
            for (int q = 0; q < 4; q++) acc[mi][ni][q] = 0.f;

    float4 pa0 = make_float4(0.f, 0.f, 0.f, 0.f), pa1 = pa0;
    if (aValid) { pa0 = *(const float4*)Aptr; pa1 = *(const float4*)(Aptr + 4); }
    float4 pb = *(const float4*)Bptr;

    for (int k0 = 0; k0 < K; k0 += 16) {
        As[aRow][aCol + 0] = f2tf(pa0.x); As[aRow][aCol + 1] = f2tf(pa0.y);
        As[aRow][aCol + 2] = f2tf(pa0.z); As[aRow][aCol + 3] = f2tf(pa0.w);
        As[aRow][aCol + 4] = f2tf(pa1.x); As[aRow][aCol + 5] = f2tf(pa1.y);
        As[aRow][aCol + 6] = f2tf(pa1.z); As[aRow][aCol + 7] = f2tf(pa1.w);
        Bs[bRow][bCol + 0] = f2tf(pb.x);  Bs[bRow][bCol + 1] = f2tf(pb.y);
        Bs[bRow][bCol + 2] = f2tf(pb.z);  Bs[bRow][bCol + 3] = f2tf(pb.w);
        __syncthreads();

        if (k0 + 16 < K) {
            if (aValid) {
                pa0 = *(const float4*)(Aptr + k0 + 16);
                pa1 = *(const float4*)(Aptr + k0 + 20);
            }
            pb = *(const float4*)(Bptr + (size_t)(k0 + 16) * N);
        }

#pragma unroll
        for (int ks = 0; ks < 16; ks += 8) {
            uint32_t af[2][4], bf[4][2];
#pragma unroll
            for (int mi = 0; mi < 2; mi++) {
                int rb = wm + mi * 16;
                af[mi][0] = As[rb + g][ks + t4];
                af[mi][1] = As[rb + g + 8][ks + t4];
                af[mi][2] = As[rb + g][ks + t4 + 4];
                af[mi][3] = As[rb + g + 8][ks + t4 + 4];
            }
#pragma unroll
            for (int ni = 0; ni < 4; ni++) {
                int cb = wn + ni * 8 + g;
                bf[ni][0] = Bs[ks + t4][cb];
                bf[ni][1] = Bs[ks + t4 + 4][cb];
            }
#pragma unroll
            for (int mi = 0; mi < 2; mi++)
#pragma unroll
                for (int ni = 0; ni < 4; ni++)
                    mma_tf32(acc[mi][ni][0], acc[mi][ni][1], acc[mi][ni][2], acc[mi][ni][3],
                             af[mi][0], af[mi][1], af[mi][2], af[mi][3],
                             bf[ni][0], bf[ni][1]);
        }
        __syncthreads();
    }

    // epilogue: c0,c1 -> (row, col..col+1); c2,c3 -> (row+8, col..col+1)
#pragma unroll
    for (int mi = 0; mi < 2; mi++) {
#pragma unroll
        for (int ni = 0; ni < 4; ni++) {
            int col = bn0 + wn + ni * 8 + 2 * t4;
            float bx = bias ? bias[col] : 0.f;
            float by = bias ? bias[col + 1] : 0.f;
#pragma unroll
            for (int h = 0; h < 2; h++) {
                int r = bm0 + wm + mi * 16 + g + h * 8;
                if (r >= M) continue;
                float v0 = acc[mi][ni][2 * h + 0] + bx;
                float v1 = acc[mi][ni][2 * h + 1] + by;
                if (relu) { v0 = fmaxf(v0, 0.f); v1 = fmaxf(v1, 0.f); }
                if (res) {
                    v0 += res[(size_t)r * N + col];
                    v1 += res[(size_t)r * N + col + 1];
                }
                *(float2*)(C + (size_t)r * N + col) = make_float2(v0, v1);
            }
        }
    }
}

// ---------------- attention (segment softmax over batch) ----------------
__device__ __forceinline__ void atomicMaxF(float* addr, float v) {
    if (v >= 0.f) atomicMax((int*)addr, __float_as_int(v));
    else          atomicMin((unsigned int*)addr, __float_as_uint(v));
}

__global__ void att_max_kernel(int gateSel, const int* __restrict__ batch, int total) {
    int idx = blockIdx.x * blockDim.x + threadIdx.x;
    if (idx >= total) return;
    int i = idx / 192, f = idx - i * 192;
    atomicMaxF(&scratch(SEL_GMAX)[batch[i] * 192 + f], scratch(gateSel)[idx]);
}

__global__ void att_exp_kernel(int gateSel, const int* __restrict__ batch, int total) {
    int idx = blockIdx.x * blockDim.x + threadIdx.x;
    if (idx >= total) return;
    int i = idx / 192, f = idx - i * 192;
    float* gate = scratch(gateSel);
    float e = expf(gate[idx] - scratch(SEL_GMAX)[batch[i] * 192 + f]);
    gate[idx] = e;
    atomicAdd(&scratch(SEL_ESUM)[batch[i] * 192 + f], e);
}

__global__ void att_zg_kernel(int gateSel, int zSel, const int* __restrict__ batch, int total) {
    int idx = blockIdx.x * blockDim.x + threadIdx.x;
    if (idx >= total) return;
    int i = idx / 192, f = idx - i * 192;
    int bf = batch[i] * 192 + f;
    atomicAdd(&scratch(SEL_ZG)[bf],
              scratch(gateSel)[idx] * scratch(zSel)[idx] / scratch(SEL_ESUM)[bf]);
}

// ---------------- launch helpers ----------------
static inline void launch_fill(int sel, float v, int n) {
    int n4 = n >> 2;
    fill_kernel<<<(n4 + 255) / 256, 256>>>(sel, v, n4);
}
static inline void launch_gemm(int M, int N, int K,
                               const float* Aext, int Asel, const float* B,
                               const float* bias, int resSel,
                               float* Cext, int Csel, int relu) {
    dim3 grid((N + 63) / 64, (M + 127) / 128);
    tgemm_kernel<<<grid, 256>>>(M, N, K, Aext, Asel, B, bias, resSel, Cext, Csel, relu);
}

extern "C" void kernel_launch(void* const* d_in, const int* in_sizes, int n_in,
                              void* d_out, int out_size) {
    const float* x1    = (const float*)d_in[0];
    const float* x2    = (const float*)d_in[1];
    const float* pe    = (const float*)d_in[2];
    const int*   ei    = (const int*)d_in[3];
    const int*   batch = (const int*)d_in[4];
    const float *Wc  = (const float*)d_in[5],  *bc  = (const float*)d_in[6];
    const float *Wmf = (const float*)d_in[7],  *bmf = (const float*)d_in[8];
    const float *Wgf = (const float*)d_in[9],  *bgf = (const float*)d_in[10];
    const float *Wmc = (const float*)d_in[11], *bmc = (const float*)d_in[12];
    const float *Wgc = (const float*)d_in[13], *bgc = (const float*)d_in[14];
    const float *Wa1 = (const float*)d_in[15], *ba1 = (const float*)d_in[16];
    const float *Wa2 = (const float*)d_in[17], *ba2 = (const float*)d_in[18];
    const float *Wgd = (const float*)d_in[19], *bgd = (const float*)d_in[20];
    const float *Wd1 = (const float*)d_in[21], *bd1 = (const float*)d_in[22];
    const float *Wd2 = (const float*)d_in[23], *bd2 = (const float*)d_in[24];
    const float *Wd3 = (const float*)d_in[25], *bd3 = (const float*)d_in[26];
    float* out = (float*)d_out;

    const int* src = ei;
    const int* dst = ei + NE;

    const int NODE192 = NN * 48;
    const int NODE32  = NN * 8;
    const int N192    = NN * 192;
    const int BLK = 256;

    // ---- CSR build (multi-block scan) ----
    zero_pos_kernel<<<(NN + BLK - 1) / BLK, BLK>>>();
    count_deg_kernel<<<(NE + BLK - 1) / BLK, BLK>>>(dst);
    dinv_kernel<<<(NN + BLK - 1) / BLK, BLK>>>();
    scan1_kernel<<<NSCAN_BLK, 1024>>>();
    scan2_kernel<<<1, 128>>>();
    scan3_kernel<<<NSCAN_BLK, 1024>>>();
    csr_fill_kernel<<<(NE + BLK - 1) / BLK, BLK>>>(src, dst);

    // ---- encoder ----
    launch_gemm(NN, 192, 384, x1, -1, Wc, bc, -1, nullptr, 0, 1);
    gather_add_kernel<<<(NODE192 + BLK - 1) / BLK, BLK>>>(nullptr, 0, pe, 1, 48, 192, NODE192);
    launch_gemm(NN, 256, 192, nullptr, 1, Wmf, bmf, -1, nullptr, 2, 1);
    launch_gemm(NN, 192, 256, nullptr, 2, Wgf, nullptr, -1, nullptr, 3, 0);
    gather_gcn_kernel<<<(NODE192 + BLK - 1) / BLK, BLK>>>(3, bgf, 4, NODE192);
    gather_add_kernel<<<(NODE32 + BLK - 1) / BLK, BLK>>>(x2, -1, nullptr, 1, 8, 32, NODE32);
    launch_gemm(NN, 64, 32, nullptr, 1, Wmc, bmc, -1, nullptr, 2, 1);
    launch_gemm(NN, 192, 64, nullptr, 2, Wgc, nullptr, -1, nullptr, 3, 0);
    gather_gcn_kernel<<<(NODE192 + BLK - 1) / BLK, BLK>>>(3, bgc, 5, NODE192);
    add3_kernel<<<(N192 + BLK - 1) / BLK, BLK>>>(4, 5, 0, 4, N192);

    // ---- attentional aggregation ----
    launch_gemm(NN, 256, 192, nullptr, 4, Wa1, ba1, -1, nullptr, 2, 1);
    launch_gemm(NN, 192, 256, nullptr, 2, Wa2, ba2, -1, nullptr, 3, 0);
    launch_fill(SEL_GMAX, -FLT_MAX, NG * 192);
    launch_fill(SEL_ESUM, 0.f, NG * 192);
    launch_fill(SEL_ZG,   0.f, NG * 192);
    att_max_kernel<<<(N192 + BLK - 1) / BLK, BLK>>>(3, batch, N192);
    att_exp_kernel<<<(N192 + BLK - 1) / BLK, BLK>>>(3, batch, N192);
    att_zg_kernel<<<(N192 + BLK - 1) / BLK, BLK>>>(3, 4, batch, N192);

    // ---- decoder ----
    launch_gemm(NG, 192, 192, nullptr, SEL_ZG, Wgd, nullptr, -1, nullptr, SEL_ZGW, 0);
    gather_gcn_bcast_kernel<<<(NODE192 + BLK - 1) / BLK, BLK>>>(SEL_ZGW, batch, bgd, 5, NODE192);
    gather_add_kernel<<<(NODE192 + BLK - 1) / BLK, BLK>>>(nullptr, 5, pe, 1, 48, 192, NODE192);
    launch_gemm(NN, 192, 192, nullptr, 1, Wd1, bd1, -1, nullptr, 2, 1);
    gather_add_kernel<<<(NODE192 + BLK - 1) / BLK, BLK>>>(nullptr, 2, nullptr, 1, 48, 192, NODE192);
    launch_gemm(NN, 192, 192, nullptr, 1, Wd2, bd2, 5, nullptr, 3, 1);
    gather_add_kernel<<<(NODE192 + BLK - 1) / BLK, BLK>>>(nullptr, 3, nullptr, 1, 48, 192, NODE192);
    launch_gemm(NN, 384, 192, nullptr, 1, Wd3, bd3, -1, out, -1, 1);
}

// round 6
// speedup vs baseline: 2.9405x; 1.3057x over previous
#include <cuda_runtime.h>
#include <math.h>
#include <float.h>
#include <stdint.h>

#define NN 100000
#define NE 800000
#define NG 64
#define NSCAN_BLK 98   // ceil(NN/1024)

// ---------------- scratch pool (device globals; resolved device-side) ----------------
__device__ float g_B0[NN * 192];   // x1_res
__device__ float g_B1[NN * 192];   // agg (gather target)
__device__ float g_B2[NN * 256];   // h -> c -> tmp -> t
__device__ float g_B3[NN * 192];   // hw -> gate -> t2
__device__ float g_B4[NN * 192];   // h2 -> z
__device__ float g_B5[NN * 192];   // c2 -> z1_res
__device__ float g_dinv[NN];
__device__ float g_small[2 * NG * 192];  // zg | zgw
__device__ int   g_rowptr[NN + 1];
__device__ int   g_pos[NN];
__device__ int   g_bsum[128];
__device__ int   g_gstart[NG + 1];
__device__ int   g_csrc[NE];

#define SEL_ZG   16
#define SEL_ZGW  19

__device__ __forceinline__ float* scratch(int id) {
    switch (id) {
        case 0:  return g_B0;
        case 1:  return g_B1;
        case 2:  return g_B2;
        case 3:  return g_B3;
        case 4:  return g_B4;
        case 5:  return g_B5;
        case SEL_ZG:   return g_small;
        case SEL_ZGW:  return g_small + NG * 192;
        default: return nullptr;
    }
}

// ---------------- CSR build ----------------
__global__ void zero_pos_kernel() {
    int i = blockIdx.x * blockDim.x + threadIdx.x;
    if (i < NN) g_pos[i] = 0;
}

__global__ void count_deg_kernel(const int* __restrict__ dst) {
    int e = blockIdx.x * blockDim.x + threadIdx.x;
    if (e < NE) atomicAdd(&g_pos[dst[e]], 1);
}

__global__ void dinv_kernel() {
    int i = blockIdx.x * blockDim.x + threadIdx.x;
    if (i < NN) g_dinv[i] = rsqrtf((float)g_pos[i] + 1.0f);
}

__global__ void scan1_kernel() {
    __shared__ int s[1024];
    int tid = threadIdx.x;
    int idx = blockIdx.x * 1024 + tid;
    int v = (idx < NN) ? g_pos[idx] : 0;
    s[tid] = v;
    __syncthreads();
    for (int off = 1; off < 1024; off <<= 1) {
        int t = (tid >= off) ? s[tid - off] : 0;
        __syncthreads();
        s[tid] += t;
        __syncthreads();
    }
    if (idx < NN) g_rowptr[idx] = s[tid] - v;
    if (tid == 1023) g_bsum[blockIdx.x] = s[1023];
}

__global__ void scan2_kernel() {
    __shared__ int s[128];
    int tid = threadIdx.x;
    int v = (tid < NSCAN_BLK) ? g_bsum[tid] : 0;
    s[tid] = v;
    __syncthreads();
    for (int off = 1; off < 128; off <<= 1) {
        int t = (tid >= off) ? s[tid - off] : 0;
        __syncthreads();
        s[tid] += t;
        __syncthreads();
    }
    if (tid < NSCAN_BLK) g_bsum[tid] = s[tid] - v;
    if (tid == 127) g_rowptr[NN] = s[127];
}

__global__ void scan3_kernel() {
    int idx = blockIdx.x * 1024 + threadIdx.x;
    if (idx < NN) {
        int r = g_rowptr[idx] + g_bsum[blockIdx.x];
        g_rowptr[idx] = r;
        g_pos[idx] = r;
    }
}

__global__ void csr_fill_kernel(const int* __restrict__ src, const int* __restrict__ dst) {
    int e = blockIdx.x * blockDim.x + threadIdx.x;
    if (e >= NE) return;
    int p = atomicAdd(&g_pos[dst[e]], 1);
    g_csrc[p] = src[e];
}

// graph segment starts via binary search (batch is sorted)
__global__ void gstart_kernel(const int* __restrict__ batch) {
    int g = threadIdx.x;
    if (g > NG) return;
    int lo = 0, hi = NN;
    while (lo < hi) {
        int mid = (lo + hi) >> 1;
        if (batch[mid] < g) lo = mid + 1; else hi = mid;
    }
    g_gstart[g] = lo;
}

// ---------------- gather kernels (CSR, no atomics) ----------------
__global__ void gather_add_kernel(const float* __restrict__ xext, int xSel,
                                  const float* __restrict__ pe,
                                  int aggSel, int D4, int D, int total) {
    int tid = blockIdx.x * blockDim.x + threadIdx.x;
    if (tid >= total) return;
    const float* x = xext ? xext : scratch(xSel);
    float* agg = scratch(aggSel);
    int i = tid / D4;
    int c = (tid - i * D4) << 2;
    int beg = g_rowptr[i], end = g_rowptr[i + 1];
    float4 acc = make_float4(0.f, 0.f, 0.f, 0.f);
    for (int e = beg; e < end; e++) {
        int s = g_csrc[e];
        float4 v = *(const float4*)(x + (size_t)s * D + c);
        if (pe) {
            float4 p = *(const float4*)(pe + (size_t)s * 64 + (c & 63));
            v.x += p.x; v.y += p.y; v.z += p.z; v.w += p.w;
        }
        acc.x += v.x; acc.y += v.y; acc.z += v.z; acc.w += v.w;
    }
    *(float4*)(agg + (size_t)i * D + c) = acc;
}

// fused GCN: out = relu(dinv[i]*sum(hw[s]*dinv[s]) + hw[i]*dinv[i]^2 + b) [+ add1 + add2]
__global__ void gather_gcn_kernel(int hwSel, const float* __restrict__ b,
                                  int outSel, int add1Sel, int add2Sel, int total) {
    int tid = blockIdx.x * blockDim.x + threadIdx.x;
    if (tid >= total) return;
    const float* hw = scratch(hwSel);
    float* out = scratch(outSel);
    int i = tid / 48;
    int c = (tid - i * 48) << 2;
    int beg = g_rowptr[i], end = g_rowptr[i + 1];
    float4 acc = make_float4(0.f, 0.f, 0.f, 0.f);
    for (int e = beg; e < end; e++) {
        int s = g_csrc[e];
        float w = g_dinv[s];
        float4 v = *(const float4*)(hw + (size_t)s * 192 + c);
        acc.x += v.x * w; acc.y += v.y * w; acc.z += v.z * w; acc.w += v.w * w;
    }
    float di = g_dinv[i];
    float dii = di * di;
    float4 sv = *(const float4*)(hw + (size_t)i * 192 + c);
    float4 bb = *(const float4*)(b + c);
    float4 o;
    size_t idx = (size_t)i * 192 + c;
    o.x = fmaxf(acc.x * di + sv.x * dii + bb.x, 0.f);
    o.y = fmaxf(acc.y * di + sv.y * dii + bb.y, 0.f);
    o.z = fmaxf(acc.z * di + sv.z * dii + bb.z, 0.f);
    o.w = fmaxf(acc.w * di + sv.w * dii + bb.w, 0.f);
    if (add1Sel >= 0) {
        float4 a1 = *(const float4*)(scratch(add1Sel) + idx);
        float4 a2 = *(const float4*)(scratch(add2Sel) + idx);
        o.x += a1.x + a2.x; o.y += a1.y + a2.y;
        o.z += a1.z + a2.z; o.w += a1.w + a2.w;
    }
    *(float4*)(out + idx) = o;
}

__global__ void gather_gcn_bcast_kernel(int zgwSel, const int* __restrict__ batch,
                                        const float* __restrict__ b,
                                        int outSel, int total) {
    int tid = blockIdx.x * blockDim.x + threadIdx.x;
    if (tid >= total) return;
    const float* zgw = scratch(zgwSel);
    float* out = scratch(outSel);
    int i = tid / 48;
    int c = (tid - i * 48) << 2;
    int beg = g_rowptr[i], end = g_rowptr[i + 1];
    float4 acc = make_float4(0.f, 0.f, 0.f, 0.f);
    for (int e = beg; e < end; e++) {
        int s = g_csrc[e];
        float w = g_dinv[s];
        float4 v = *(const float4*)(zgw + (size_t)batch[s] * 192 + c);
        acc.x += v.x * w; acc.y += v.y * w; acc.z += v.z * w; acc.w += v.w * w;
    }
    float di = g_dinv[i];
    float dii = di * di;
    float4 sv = *(const float4*)(zgw + (size_t)batch[i] * 192 + c);
    float4 bb = *(const float4*)(b + c);
    float4 o;
    o.x = fmaxf(acc.x * di + sv.x * dii + bb.x, 0.f);
    o.y = fmaxf(acc.y * di + sv.y * dii + bb.y, 0.f);
    o.z = fmaxf(acc.z * di + sv.z * dii + bb.z, 0.f);
    o.w = fmaxf(acc.w * di + sv.w * dii + bb.w, 0.f);
    *(float4*)(out + (size_t)i * 192 + c) = o;
}

// ---------------- fused attention: one block per graph, thread = feature ----------------
__global__ void att_fused_kernel(int gateSel, int zSel) {
    int gph = blockIdx.x;
    int f = threadIdx.x;   // 0..191
    const float* gate = scratch(gateSel);
    const float* z = scratch(zSel);
    float* zg = scratch(SEL_ZG);
    int n0 = g_gstart[gph], n1 = g_gstart[gph + 1];
    if (n0 >= n1) { zg[gph * 192 + f] = 0.f; return; }

    // pass 1: max (4 independent accumulators for MLP)
    float m0 = -FLT_MAX, m1 = -FLT_MAX, m2 = -FLT_MAX, m3 = -FLT_MAX;
    int n = n0;
    for (; n + 3 < n1; n += 4) {
        m0 = fmaxf(m0, gate[(size_t)(n + 0) * 192 + f]);
        m1 = fmaxf(m1, gate[(size_t)(n + 1) * 192 + f]);
        m2 = fmaxf(m2, gate[(size_t)(n + 2) * 192 + f]);
        m3 = fmaxf(m3, gate[(size_t)(n + 3) * 192 + f]);
    }
    for (; n < n1; n++) m0 = fmaxf(m0, gate[(size_t)n * 192 + f]);
    float m = fmaxf(fmaxf(m0, m1), fmaxf(m2, m3));

    // pass 2: exp-sum and weighted sum
    float es0 = 0.f, es1 = 0.f, ez0 = 0.f, ez1 = 0.f;
    n = n0;
    for (; n + 1 < n1; n += 2) {
        size_t i0 = (size_t)n * 192 + f, i1 = (size_t)(n + 1) * 192 + f;
        float e0 = expf(gate[i0] - m);
        float e1 = expf(gate[i1] - m);
        es0 += e0; ez0 += e0 * z[i0];
        es1 += e1; ez1 += e1 * z[i1];
    }
    if (n < n1) {
        size_t i0 = (size_t)n * 192 + f;
        float e0 = expf(gate[i0] - m);
        es0 += e0; ez0 += e0 * z[i0];
    }
    zg[gph * 192 + f] = (ez0 + ez1) / (es0 + es1);
}

// ---------------- TF32 tensor-core GEMM ----------------
// BM=256, BN=64, BK=16; 8 warps as 4(M)x2(N), each 64x32. mma.m16n8k8 tf32.
__device__ __forceinline__ uint32_t f2tf(float f) {
    uint32_t u;
    asm("cvt.rna.tf32.f32 %0, %1;" : "=r"(u) : "f"(f));
    return u;
}

__device__ __forceinline__ void mma_tf32(float& c0, float& c1, float& c2, float& c3,
                                         uint32_t a0, uint32_t a1, uint32_t a2, uint32_t a3,
                                         uint32_t b0, uint32_t b1) {
    asm volatile(
        "mma.sync.aligned.m16n8k8.row.col.f32.tf32.tf32.f32 "
        "{%0,%1,%2,%3},{%4,%5,%6,%7},{%8,%9},{%0,%1,%2,%3};\n"
        : "+f"(c0), "+f"(c1), "+f"(c2), "+f"(c3)
        : "r"(a0), "r"(a1), "r"(a2), "r"(a3), "r"(b0), "r"(b1));
}

__global__ __launch_bounds__(256)
void tgemm_kernel(int M, int N, int K,
                  const float* __restrict__ Aext, int Asel,
                  const float* __restrict__ B,
                  const float* __restrict__ bias,
                  int resSel,
                  float* __restrict__ Cext, int Csel,
                  int relu) {
    __shared__ uint32_t As[256][20];  // [m][k], stride 20 -> conflict-free frag loads
    __shared__ uint32_t Bs[16][72];   // [k][n], stride 72 -> conflict-free frag loads

    const float* A = Aext ? Aext : scratch(Asel);
    float* C = Cext ? Cext : scratch(Csel);
    const float* res = (resSel >= 0) ? scratch(resSel) : nullptr;

    int tid = threadIdx.x;
    int bm0 = blockIdx.y * 256, bn0 = blockIdx.x * 64;
    int lane = tid & 31, wid = tid >> 5;
    int g = lane >> 2, t4 = lane & 3;
    int wm = (wid & 3) * 64;    // warp m-offset (4 warps down M)
    int wn = (wid >> 2) * 32;   // warp n-offset (2 warps across N)

    // A: 256x16 floats = 1024 float4, 4 per thread (4 consecutive threads per row)
    int aRow[4], aCol[4];
    bool aOk[4];
#pragma unroll
    for (int q = 0; q < 4; q++) {
        int fid = tid + 256 * q;
        aRow[q] = fid >> 2;
        aCol[q] = (fid & 3) << 2;
        aOk[q] = (bm0 + aRow[q]) < M;
    }
    int bRow = tid >> 4, bCol = (tid & 15) << 2;
    const float* Bptr = B + (size_t)bRow * N + bn0 + bCol;

    float acc[4][4][4];
#pragma unroll
    for (int mi = 0; mi < 4; mi++)
#pragma unroll
        for (int ni = 0; ni < 4; ni++)
#pragma unroll
            for (int q = 0; q < 4; q++) acc[mi][ni][q] = 0.f;

    float4 pa[4];
#pragma unroll
    for (int q = 0; q < 4; q++) {
        pa[q] = make_float4(0.f, 0.f, 0.f, 0.f);
        if (aOk[q]) pa[q] = *(const float4*)(A + (size_t)(bm0 + aRow[q]) * K + aCol[q]);
    }
    float4 pb = *(const float4*)Bptr;

    for (int k0 = 0; k0 < K; k0 += 16) {
#pragma unroll
        for (int q = 0; q < 4; q++) {
            As[aRow[q]][aCol[q] + 0] = f2tf(pa[q].x);
            As[aRow[q]][aCol[q] + 1] = f2tf(pa[q].y);
            As[aRow[q]][aCol[q] + 2] = f2tf(pa[q].z);
            As[aRow[q]][aCol[q] + 3] = f2tf(pa[q].w);
        }
        Bs[bRow][bCol + 0] = f2tf(pb.x); Bs[bRow][bCol + 1] = f2tf(pb.y);
        Bs[bRow][bCol + 2] = f2tf(pb.z); Bs[bRow][bCol + 3] = f2tf(pb.w);
        __syncthreads();

        if (k0 + 16 < K) {
#pragma unroll
            for (int q = 0; q < 4; q++)
                if (aOk[q]) pa[q] = *(const float4*)(A + (size_t)(bm0 + aRow[q]) * K + k0 + 16 + aCol[q]);
            pb = *(const float4*)(Bptr + (size_t)(k0 + 16) * N);
        }

#pragma unroll
        for (int ks = 0; ks < 16; ks += 8) {
            uint32_t af[4][4], bf[4][2];
#pragma unroll
            for (int mi = 0; mi < 4; mi++) {
                int rb = wm + mi * 16;
                af[mi][0] = As[rb + g][ks + t4];
                af[mi][1] = As[rb + g + 8][ks + t4];
                af[mi][2] = As[rb + g][ks + t4 + 4];
                af[mi][3] = As[rb + g + 8][ks + t4 + 4];
            }
#pragma unroll
            for (int ni = 0; ni < 4; ni++) {
                int cb = wn + ni * 8 + g;
                bf[ni][0] = Bs[ks + t4][cb];
                bf[ni][1] = Bs[ks + t4 + 4][cb];
            }
#pragma unroll
            for (int mi = 0; mi < 4; mi++)
#pragma unroll
                for (int ni = 0; ni < 4; ni++)
                    mma_tf32(acc[mi][ni][0], acc[mi][ni][1], acc[mi][ni][2], acc[mi][ni][3],
                             af[mi][0], af[mi][1], af[mi][2], af[mi][3],
                             bf[ni][0], bf[ni][1]);
        }
        __syncthreads();
    }

#pragma unroll
    for (int mi = 0; mi < 4; mi++) {
#pragma unroll
        for (int ni = 0; ni < 4; ni++) {
            int col = bn0 + wn + ni * 8 + 2 * t4;
            float bx = bias ? bias[col] : 0.f;
            float by = bias ? bias[col + 1] : 0.f;
#pragma unroll
            for (int h = 0; h < 2; h++) {
                int r = bm0 + wm + mi * 16 + g + h * 8;
                if (r >= M) continue;
                float v0 = acc[mi][ni][2 * h + 0] + bx;
                float v1 = acc[mi][ni][2 * h + 1] + by;
                if (relu) { v0 = fmaxf(v0, 0.f); v1 = fmaxf(v1, 0.f); }
                if (res) {
                    v0 += res[(size_t)r * N + col];
                    v1 += res[(size_t)r * N + col + 1];
                }
                *(float2*)(C + (size_t)r * N + col) = make_float2(v0, v1);
            }
        }
    }
}

// ---------------- launch helpers ----------------
static inline void launch_gemm(int M, int N, int K,
                               const float* Aext, int Asel, const float* B,
                               const float* bias, int resSel,
                               float* Cext, int Csel, int relu) {
    dim3 grid((N + 63) / 64, (M + 255) / 256);
    tgemm_kernel<<<grid, 256>>>(M, N, K, Aext, Asel, B, bias, resSel, Cext, Csel, relu);
}

extern "C" void kernel_launch(void* const* d_in, const int* in_sizes, int n_in,
                              void* d_out, int out_size) {
    const float* x1    = (const float*)d_in[0];
    const float* x2    = (const float*)d_in[1];
    const float* pe    = (const float*)d_in[2];
    const int*   ei    = (const int*)d_in[3];
    const int*   batch = (const int*)d_in[4];
    const float *Wc  = (const float*)d_in[5],  *bc  = (const float*)d_in[6];
    const float *Wmf = (const float*)d_in[7],  *bmf = (const float*)d_in[8];
    const float *Wgf = (const float*)d_in[9],  *bgf = (const float*)d_in[10];
    const float *Wmc = (const float*)d_in[11], *bmc = (const float*)d_in[12];
    const float *Wgc = (const float*)d_in[13], *bgc = (const float*)d_in[14];
    const float *Wa1 = (const float*)d_in[15], *ba1 = (const float*)d_in[16];
    const float *Wa2 = (const float*)d_in[17], *ba2 = (const float*)d_in[18];
    const float *Wgd = (const float*)d_in[19], *bgd = (const float*)d_in[20];
    const float *Wd1 = (const float*)d_in[21], *bd1 = (const float*)d_in[22];
    const float *Wd2 = (const float*)d_in[23], *bd2 = (const float*)d_in[24];
    const float *Wd3 = (const float*)d_in[25], *bd3 = (const float*)d_in[26];
    float* out = (float*)d_out;

    const int* src = ei;
    const int* dst = ei + NE;

    const int NODE192 = NN * 48;
    const int NODE32  = NN * 8;
    const int BLK = 256;

    // ---- CSR build + graph segment bounds ----
    zero_pos_kernel<<<(NN + BLK - 1) / BLK, BLK>>>();
    gstart_kernel<<<1, NG + 1>>>(batch);
    count_deg_kernel<<<(NE + BLK - 1) / BLK, BLK>>>(dst);
    dinv_kernel<<<(NN + BLK - 1) / BLK, BLK>>>();
    scan1_kernel<<<NSCAN_BLK, 1024>>>();
    scan2_kernel<<<1, 128>>>();
    scan3_kernel<<<NSCAN_BLK, 1024>>>();
    csr_fill_kernel<<<(NE + BLK - 1) / BLK, BLK>>>(src, dst);

    // ---- encoder ----
    launch_gemm(NN, 192, 384, x1, -1, Wc, bc, -1, nullptr, 0, 1);
    gather_add_kernel<<<(NODE192 + BLK - 1) / BLK, BLK>>>(nullptr, 0, pe, 1, 48, 192, NODE192);
    launch_gemm(NN, 256, 192, nullptr, 1, Wmf, bmf, -1, nullptr, 2, 1);
    launch_gemm(NN, 192, 256, nullptr, 2, Wgf, nullptr, -1, nullptr, 3, 0);
    gather_gcn_kernel<<<(NODE192 + BLK - 1) / BLK, BLK>>>(3, bgf, 4, -1, -1, NODE192);
    gather_add_kernel<<<(NODE32 + BLK - 1) / BLK, BLK>>>(x2, -1, nullptr, 1, 8, 32, NODE32);
    launch_gemm(NN, 64, 32, nullptr, 1, Wmc, bmc, -1, nullptr, 2, 1);
    launch_gemm(NN, 192, 64, nullptr, 2, Wgc, nullptr, -1, nullptr, 3, 0);
    // z = relu(gcn_c) + h2 + x1res  (fused add3) -> B4
    gather_gcn_kernel<<<(NODE192 + BLK - 1) / BLK, BLK>>>(3, bgc, 4, 4, 0, NODE192);

    // ---- attentional aggregation (atomic-free) ----
    launch_gemm(NN, 256, 192, nullptr, 4, Wa1, ba1, -1, nullptr, 2, 1);
    launch_gemm(NN, 192, 256, nullptr, 2, Wa2, ba2, -1, nullptr, 3, 0);
    att_fused_kernel<<<NG, 192>>>(3, 4);

    // ---- decoder ----
    launch_gemm(NG, 192, 192, nullptr, SEL_ZG, Wgd, nullptr, -1, nullptr, SEL_ZGW, 0);
    gather_gcn_bcast_kernel<<<(NODE192 + BLK - 1) / BLK, BLK>>>(SEL_ZGW, batch, bgd, 5, NODE192);
    gather_add_kernel<<<(NODE192 + BLK - 1) / BLK, BLK>>>(nullptr, 5, pe, 1, 48, 192, NODE192);
    launch_gemm(NN, 192, 192, nullptr, 1, Wd1, bd1, -1, nullptr, 2, 1);
    gather_add_kernel<<<(NODE192 + BLK - 1) / BLK, BLK>>>(nullptr, 2, nullptr, 1, 48, 192, NODE192);
    launch_gemm(NN, 192, 192, nullptr, 1, Wd2, bd2, 5, nullptr, 3, 1);
    gather_add_kernel<<<(NODE192 + BLK - 1) / BLK, BLK>>>(nullptr, 3, nullptr, 1, 48, 192, NODE192);
    launch_gemm(NN, 384, 192, nullptr, 1, Wd3, bd3, -1, out, -1, 1);
}